// round 15
// baseline (speedup 1.0000x reference)
#include <cuda_runtime.h>
#include <cuda_bf16.h>
#include <cstdint>

// LSTMNet: B=1024, T=2048, H=64, NC=10
// 128-thread CTA per batch element, occupancy 3.
// Gate pairing (R14): thread (hid = t>>1, p = t&1):
//   p=0 owns rows {i, g} of hid ; p=1 owns rows {f, o}.
//   p0 computes i*g locally -> ONE shfl ships it to p1, which owns f, o and
//   the cell state c: c = f*c + (i*g); h = o * tanh(c); p1 stores h.
// 4-way accumulator split per row: FMA2 dependency depth 16 -> 4.
// Sigmoid rows' weights/bias pre-scaled by 0.5 (activation = tanh directly);
// input projection folded into accumulator init. One __syncthreads per step.

#define T_LEN 2048
#define HDIM  64
#define NCLS  10

#define FMA2(acc, a, b) \
    asm("fma.rn.f32x2 %0, %1, %2, %0;" : "+l"(acc) : "l"(a), "l"(b))
#define ADD2(d, a, b) \
    asm("add.rn.f32x2 %0, %1, %2;" : "=l"(d) : "l"(a), "l"(b))
#define MUL2(d, a, b) \
    asm("mul.rn.f32x2 %0, %1, %2;" : "=l"(d) : "l"(a), "l"(b))

__device__ __forceinline__ float tanh_fast(float z) {
    float r;
    asm("tanh.approx.f32 %0, %1;" : "=f"(r) : "f"(z));
    return r;
}

__device__ __forceinline__ float pair_sum(unsigned long long a) {
    return __uint_as_float((unsigned)a) + __uint_as_float((unsigned)(a >> 32));
}

__device__ __forceinline__ unsigned long long pack_lo(float x) {
    return (unsigned long long)__float_as_uint(x);   // (x, 0.0f)
}

__global__ __launch_bounds__(128, 3)
void lstm_net_kernel(const float* __restrict__ x,
                     const float* __restrict__ W_ih,
                     const float* __restrict__ W_hh,
                     const float* __restrict__ b_ih,
                     const float* __restrict__ b_hh,
                     const float* __restrict__ fc1_w,
                     const float* __restrict__ fc1_b,
                     const float* __restrict__ fc2_w,
                     const float* __restrict__ fc2_b,
                     float* __restrict__ out)
{
    __shared__ __align__(16) float sx[T_LEN];      // x row (8 KB)
    __shared__ __align__(16) float sh[2][HDIM];    // double-buffered hidden
    __shared__ __align__(16) float s1[HDIM];       // fc1 out

    const int b   = blockIdx.x;
    const int t   = threadIdx.x;
    const int hid = t >> 1;
    const int p   = t & 1;
    const int r0  = p * HDIM + hid;                // i (p=0) / f (p=1)
    const int r1  = (2 + p) * HDIM + hid;          // g (p=0) / o (p=1)

    // ---- phase-skew spin: de-convoy the 3 co-resident CTAs ----
    {
        const int n = (int)(blockIdx.x % 3u) * 60;
        float z = 1.0f;
        #pragma unroll 1
        for (int i = 0; i < n; i++) z = fmaf(z, 1.0000001f, 1e-7f);
        asm volatile("" :: "f"(z));
    }

    // ---- stage x[b,:] (coalesced float4) ----
    {
        const float4* xr = reinterpret_cast<const float4*>(x + (size_t)b * T_LEN);
        float4* sx4 = reinterpret_cast<float4*>(sx);
        #pragma unroll
        for (int i = t; i < T_LEN / 4; i += 128) sx4[i] = xr[i];
    }

    // ---- both full W_hh rows -> 64 packed u64 regs, pre-scaled ----
    // row0 (i or f): sigmoid -> scale 0.5. row1: p0 g (tanh) -> 1.0, p1 o -> 0.5.
    const float sc1 = p ? 0.5f : 1.0f;
    unsigned long long w0[32], w1[32];
    {
        unsigned long long s0p, s1p;
        {
            const unsigned uh = __float_as_uint(0.5f);
            const unsigned u1 = __float_as_uint(sc1);
            s0p = ((unsigned long long)uh << 32) | uh;
            s1p = ((unsigned long long)u1 << 32) | u1;
        }
        const ulonglong2* p0 = reinterpret_cast<const ulonglong2*>(W_hh + (size_t)r0 * HDIM);
        const ulonglong2* p1 = reinterpret_cast<const ulonglong2*>(W_hh + (size_t)r1 * HDIM);
        #pragma unroll
        for (int j = 0; j < 16; j++) {
            ulonglong2 v0 = p0[j];
            MUL2(w0[2 * j],     v0.x, s0p);
            MUL2(w0[2 * j + 1], v0.y, s0p);
            ulonglong2 v1 = p1[j];
            MUL2(w1[2 * j],     v1.x, s1p);
            MUL2(w1[2 * j + 1], v1.y, s1p);
        }
    }
    const float w_in0 = W_ih[r0] * 0.5f;
    const float w_in1 = W_ih[r1] * sc1;
    const float bias0 = (b_ih[r0] + b_hh[r0]) * 0.5f;
    const float bias1 = (b_ih[r1] + b_hh[r1]) * sc1;

    // row1 activation transform: p0 (g): tanh -> aa=1, ab=0 ; p1 (o): sigmoid.
    const float aa1 = p ? 0.5f : 1.0f;
    const float ab1 = p ? 0.5f : 0.0f;

    if (t < HDIM) sh[0][t] = 0.0f;
    float c = 0.0f;                                 // live only in p==1 lanes
    __syncthreads();

    // one LSTM step: read sh[RB], write sh[RB^1]
    #define LSTM_STEP(RB, XT)                                                        \
    {                                                                                \
        const float pre0 = fmaf((XT), w_in0, bias0);                                 \
        const float pre1 = fmaf((XT), w_in1, bias1);                                 \
        const ulonglong2* hp = reinterpret_cast<const ulonglong2*>(sh[RB]);          \
        unsigned long long A0 = pack_lo(pre0), A1 = 0ull, A2 = 0ull, A3 = 0ull;      \
        unsigned long long B0 = pack_lo(pre1), B1 = 0ull, B2 = 0ull, B3 = 0ull;      \
        _Pragma("unroll")                                                            \
        for (int j = 0; j < 4; j++) {                                                \
            ulonglong2 h0 = hp[4 * j + 0], h1 = hp[4 * j + 1];                       \
            ulonglong2 h2 = hp[4 * j + 2], h3 = hp[4 * j + 3];                       \
            FMA2(A0, w0[8 * j + 0], h0.x);  FMA2(B0, w1[8 * j + 0], h0.x);           \
            FMA2(A1, w0[8 * j + 1], h0.y);  FMA2(B1, w1[8 * j + 1], h0.y);           \
            FMA2(A2, w0[8 * j + 2], h1.x);  FMA2(B2, w1[8 * j + 2], h1.x);           \
            FMA2(A3, w0[8 * j + 3], h1.y);  FMA2(B3, w1[8 * j + 3], h1.y);           \
            FMA2(A0, w0[8 * j + 4], h2.x);  FMA2(B0, w1[8 * j + 4], h2.x);           \
            FMA2(A1, w0[8 * j + 5], h2.y);  FMA2(B1, w1[8 * j + 5], h2.y);           \
            FMA2(A2, w0[8 * j + 6], h3.x);  FMA2(B2, w1[8 * j + 6], h3.x);           \
            FMA2(A3, w0[8 * j + 7], h3.y);  FMA2(B3, w1[8 * j + 7], h3.y);           \
        }                                                                            \
        unsigned long long u0, u1, As, v0, v1, Bs;                                   \
        ADD2(u0, A0, A1);  ADD2(u1, A2, A3);  ADD2(As, u0, u1);                      \
        ADD2(v0, B0, B1);  ADD2(v1, B2, B3);  ADD2(Bs, v0, v1);                      \
        float g0 = pair_sum(As);                                                     \
        float g1 = pair_sum(Bs);                                                     \
        float act0 = fmaf(tanh_fast(g0), 0.5f, 0.5f);   /* sigmoid: i or f */        \
        float act1 = fmaf(tanh_fast(g1), aa1, ab1);     /* g (tanh) or o  */         \
        float prod = act0 * act1;                       /* p0: i*g */                \
        float ig = __shfl_xor_sync(0xffffffffu, prod, 1, 2);                         \
        if (p) {                                                                     \
            c = fmaf(act0, c, ig);                      /* f*c + i*g */              \
            sh[(RB) ^ 1][hid] = act1 * tanh_fast(c);    /* o * tanh(c) */            \
        }                                                                            \
        __syncthreads();                                                             \
    }

    #pragma unroll 1
    for (int step = 0; step < T_LEN; step += 4) {
        const float4 xv = *reinterpret_cast<const float4*>(&sx[step]);
        LSTM_STEP(0, xv.x)
        LSTM_STEP(1, xv.y)
        LSTM_STEP(0, xv.z)
        LSTM_STEP(1, xv.w)
    }
    #undef LSTM_STEP

    // T_LEN % 4 == 0: final h lives in sh[0]
    const float* hf = sh[0];

    // ---- fc1 + relu (64 threads) ----
    if (t < HDIM) {
        float a = fc1_b[t];
        const float* wr = fc1_w + t * HDIM;
        #pragma unroll 16
        for (int k = 0; k < HDIM; k++) a = fmaf(wr[k], hf[k], a);
        s1[t] = fmaxf(a, 0.0f);
    }
    __syncthreads();

    // ---- fc2 (10 threads) ----
    if (t < NCLS) {
        float a = fc2_b[t];
        const float* wr = fc2_w + t * HDIM;
        #pragma unroll 16
        for (int k = 0; k < HDIM; k++) a = fmaf(wr[k], s1[k], a);
        out[(size_t)b * NCLS + t] = a;
    }
}

extern "C" void kernel_launch(void* const* d_in, const int* in_sizes, int n_in,
                              void* d_out, int out_size)
{
    const float* x     = (const float*)d_in[0];
    const float* W_ih  = (const float*)d_in[1];
    const float* W_hh  = (const float*)d_in[2];
    const float* b_ih  = (const float*)d_in[3];
    const float* b_hh  = (const float*)d_in[4];
    const float* fc1_w = (const float*)d_in[5];
    const float* fc1_b = (const float*)d_in[6];
    const float* fc2_w = (const float*)d_in[7];
    const float* fc2_b = (const float*)d_in[8];
    float* out = (float*)d_out;

    const int B = in_sizes[0] / T_LEN;   // 1024

    lstm_net_kernel<<<B, 128>>>(x, W_ih, W_hh, b_ih, b_hh,
                                fc1_w, fc1_b, fc2_w, fc2_b, out);
}

// round 16
// speedup vs baseline: 1.0769x; 1.0769x over previous
#include <cuda_runtime.h>
#include <cuda_bf16.h>
#include <cstdint>

// LSTMNet: B=1024, T=2048, H=64, NC=10
// 128-thread CTA per batch element, occupancy 3 (~165 regs).
// R15 = R13 matvec (2 accumulators per row, depth-16 FMA2 chains — proven
// fastest) + R14 gate pairing ONLY:
//   thread (hid = t>>1, p = t&1): p=0 owns rows {i, g}; p=1 owns rows {f, o}.
//   p0 computes i*g locally -> ONE shfl ships it to p1, which owns c:
//   c = f*c + (i*g); h = o*tanh(c); p1 stores h. No select ladder.
// Sigmoid rows' weights/bias pre-scaled by 0.5 (tanh-only activations);
// input projection folded into accumulator init; CTA phase-skew spin.
// One __syncthreads per step.

#define T_LEN 2048
#define HDIM  64
#define NCLS  10

#define FMA2(acc, a, b) \
    asm("fma.rn.f32x2 %0, %1, %2, %0;" : "+l"(acc) : "l"(a), "l"(b))
#define ADD2(d, a, b) \
    asm("add.rn.f32x2 %0, %1, %2;" : "=l"(d) : "l"(a), "l"(b))
#define MUL2(d, a, b) \
    asm("mul.rn.f32x2 %0, %1, %2;" : "=l"(d) : "l"(a), "l"(b))

__device__ __forceinline__ float tanh_fast(float z) {
    float r;
    asm("tanh.approx.f32 %0, %1;" : "=f"(r) : "f"(z));
    return r;
}

__device__ __forceinline__ float pair_sum(unsigned long long a) {
    return __uint_as_float((unsigned)a) + __uint_as_float((unsigned)(a >> 32));
}

__device__ __forceinline__ unsigned long long pack_lo(float x) {
    return (unsigned long long)__float_as_uint(x);   // (x, 0.0f)
}

__global__ __launch_bounds__(128, 3)
void lstm_net_kernel(const float* __restrict__ x,
                     const float* __restrict__ W_ih,
                     const float* __restrict__ W_hh,
                     const float* __restrict__ b_ih,
                     const float* __restrict__ b_hh,
                     const float* __restrict__ fc1_w,
                     const float* __restrict__ fc1_b,
                     const float* __restrict__ fc2_w,
                     const float* __restrict__ fc2_b,
                     float* __restrict__ out)
{
    __shared__ __align__(16) float sx[T_LEN];      // x row (8 KB)
    __shared__ __align__(16) float sh[2][HDIM];    // double-buffered hidden
    __shared__ __align__(16) float s1[HDIM];       // fc1 out

    const int b   = blockIdx.x;
    const int t   = threadIdx.x;
    const int hid = t >> 1;
    const int p   = t & 1;
    const int r0  = p * HDIM + hid;                // i (p=0) / f (p=1)
    const int r1  = (2 + p) * HDIM + hid;          // g (p=0) / o (p=1)

    // ---- phase-skew spin: de-convoy the 3 co-resident CTAs ----
    {
        const int n = (int)(blockIdx.x % 3u) * 60;
        float z = 1.0f;
        #pragma unroll 1
        for (int i = 0; i < n; i++) z = fmaf(z, 1.0000001f, 1e-7f);
        asm volatile("" :: "f"(z));
    }

    // ---- stage x[b,:] (coalesced float4) ----
    {
        const float4* xr = reinterpret_cast<const float4*>(x + (size_t)b * T_LEN);
        float4* sx4 = reinterpret_cast<float4*>(sx);
        #pragma unroll
        for (int i = t; i < T_LEN / 4; i += 128) sx4[i] = xr[i];
    }

    // ---- both full W_hh rows -> 64 packed u64 regs, pre-scaled ----
    // row0 (i or f): sigmoid -> 0.5. row1: p0 g (tanh) -> 1.0, p1 o (sigm) -> 0.5.
    const float sc1 = p ? 0.5f : 1.0f;
    unsigned long long w0[32], w1[32];
    {
        unsigned long long s0p, s1p;
        {
            const unsigned uh = __float_as_uint(0.5f);
            const unsigned u1 = __float_as_uint(sc1);
            s0p = ((unsigned long long)uh << 32) | uh;
            s1p = ((unsigned long long)u1 << 32) | u1;
        }
        const ulonglong2* p0 = reinterpret_cast<const ulonglong2*>(W_hh + (size_t)r0 * HDIM);
        const ulonglong2* p1 = reinterpret_cast<const ulonglong2*>(W_hh + (size_t)r1 * HDIM);
        #pragma unroll
        for (int j = 0; j < 16; j++) {
            ulonglong2 v0 = p0[j];
            MUL2(w0[2 * j],     v0.x, s0p);
            MUL2(w0[2 * j + 1], v0.y, s0p);
            ulonglong2 v1 = p1[j];
            MUL2(w1[2 * j],     v1.x, s1p);
            MUL2(w1[2 * j + 1], v1.y, s1p);
        }
    }
    const float w_in0 = W_ih[r0] * 0.5f;
    const float w_in1 = W_ih[r1] * sc1;
    const float bias0 = (b_ih[r0] + b_hh[r0]) * 0.5f;
    const float bias1 = (b_ih[r1] + b_hh[r1]) * sc1;

    // row1 activation transform: p0 (g): tanh ; p1 (o): sigmoid.
    const float aa1 = p ? 0.5f : 1.0f;
    const float ab1 = p ? 0.5f : 0.0f;

    if (t < HDIM) sh[0][t] = 0.0f;
    float c = 0.0f;                                 // live only in p==1 lanes
    __syncthreads();

    // one LSTM step: read sh[RB], write sh[RB^1]
    #define LSTM_STEP(RB, XT)                                                        \
    {                                                                                \
        const float pre0 = fmaf((XT), w_in0, bias0);                                 \
        const float pre1 = fmaf((XT), w_in1, bias1);                                 \
        const ulonglong2* hp = reinterpret_cast<const ulonglong2*>(sh[RB]);          \
        unsigned long long A0 = pack_lo(pre0), A1 = 0ull;                            \
        unsigned long long B0 = pack_lo(pre1), B1 = 0ull;                            \
        _Pragma("unroll")                                                            \
        for (int j = 0; j < 4; j++) {                                                \
            ulonglong2 h0 = hp[4 * j + 0], h1 = hp[4 * j + 1];                       \
            ulonglong2 h2 = hp[4 * j + 2], h3 = hp[4 * j + 3];                       \
            FMA2(A0, w0[8 * j + 0], h0.x);  FMA2(B0, w1[8 * j + 0], h0.x);           \
            FMA2(A1, w0[8 * j + 1], h0.y);  FMA2(B1, w1[8 * j + 1], h0.y);           \
            FMA2(A0, w0[8 * j + 2], h1.x);  FMA2(B0, w1[8 * j + 2], h1.x);           \
            FMA2(A1, w0[8 * j + 3], h1.y);  FMA2(B1, w1[8 * j + 3], h1.y);           \
            FMA2(A0, w0[8 * j + 4], h2.x);  FMA2(B0, w1[8 * j + 4], h2.x);           \
            FMA2(A1, w0[8 * j + 5], h2.y);  FMA2(B1, w1[8 * j + 5], h2.y);           \
            FMA2(A0, w0[8 * j + 6], h3.x);  FMA2(B0, w1[8 * j + 6], h3.x);           \
            FMA2(A1, w0[8 * j + 7], h3.y);  FMA2(B1, w1[8 * j + 7], h3.y);           \
        }                                                                            \
        unsigned long long As, Bs;                                                   \
        ADD2(As, A0, A1);  ADD2(Bs, B0, B1);                                         \
        float g0 = pair_sum(As);                                                     \
        float g1 = pair_sum(Bs);                                                     \
        float act0 = fmaf(tanh_fast(g0), 0.5f, 0.5f);   /* sigmoid: i or f */        \
        float act1 = fmaf(tanh_fast(g1), aa1, ab1);     /* g (tanh) or o  */         \
        float prod = act0 * act1;                       /* p0: i*g */                \
        float ig = __shfl_xor_sync(0xffffffffu, prod, 1, 2);                         \
        if (p) {                                                                     \
            c = fmaf(act0, c, ig);                      /* f*c + i*g */              \
            sh[(RB) ^ 1][hid] = act1 * tanh_fast(c);    /* o * tanh(c) */            \
        }                                                                            \
        __syncthreads();                                                             \
    }

    #pragma unroll 1
    for (int step = 0; step < T_LEN; step += 4) {
        const float4 xv = *reinterpret_cast<const float4*>(&sx[step]);
        LSTM_STEP(0, xv.x)
        LSTM_STEP(1, xv.y)
        LSTM_STEP(0, xv.z)
        LSTM_STEP(1, xv.w)
    }
    #undef LSTM_STEP

    // T_LEN % 4 == 0: final h lives in sh[0]
    const float* hf = sh[0];

    // ---- fc1 + relu (64 threads) ----
    if (t < HDIM) {
        float a = fc1_b[t];
        const float* wr = fc1_w + t * HDIM;
        #pragma unroll 16
        for (int k = 0; k < HDIM; k++) a = fmaf(wr[k], hf[k], a);
        s1[t] = fmaxf(a, 0.0f);
    }
    __syncthreads();

    // ---- fc2 (10 threads) ----
    if (t < NCLS) {
        float a = fc2_b[t];
        const float* wr = fc2_w + t * HDIM;
        #pragma unroll 16
        for (int k = 0; k < HDIM; k++) a = fmaf(wr[k], s1[k], a);
        out[(size_t)b * NCLS + t] = a;
    }
}

extern "C" void kernel_launch(void* const* d_in, const int* in_sizes, int n_in,
                              void* d_out, int out_size)
{
    const float* x     = (const float*)d_in[0];
    const float* W_ih  = (const float*)d_in[1];
    const float* W_hh  = (const float*)d_in[2];
    const float* b_ih  = (const float*)d_in[3];
    const float* b_hh  = (const float*)d_in[4];
    const float* fc1_w = (const float*)d_in[5];
    const float* fc1_b = (const float*)d_in[6];
    const float* fc2_w = (const float*)d_in[7];
    const float* fc2_b = (const float*)d_in[8];
    float* out = (float*)d_out;

    const int B = in_sizes[0] / T_LEN;   // 1024

    lstm_net_kernel<<<B, 128>>>(x, W_ih, W_hh, b_ih, b_hh,
                                fc1_w, fc1_b, fc2_w, fc2_b, out);
}

// round 17
// speedup vs baseline: 1.1243x; 1.0440x over previous
#include <cuda_runtime.h>
#include <cuda_bf16.h>
#include <cstdint>

// LSTMNet: B=1024, T=2048, H=64, NC=10
// R16 = R13 (best: 1635us) with ONE change: the matvec emits FMA2s in PAIRS
// sharing the h operand in the same slot within a single asm statement, so
// the second FMA2 hits the operand-reuse latch -> RF-bank rt drops 3 -> 2 for
// half the FMAs (fma.rn.f32x2 reads 3 u64 = 3 even + 3 odd distinct regs,
// bank-limited rt=3; reuse removes one distinct read).
//
// Layout (R13): 128-thread CTA per batch element, occupancy 3 (~165 regs).
// Thread (hid = t>>1, p = t&1): p=0 owns rows {i, g}... (no: R13 pairing)
//   p=0 owns gate rows {i, f}; p=1 owns {g, o}; both full 64-wide W_hh rows
//   in 64 packed u64 regs. 2 accumulators per row, depth-16 chains.
// Sigmoid rows' weights/bias pre-scaled by 0.5; input projection folded into
// accumulator init; CTA phase-skew spin; one __syncthreads per step.

#define T_LEN 2048
#define HDIM  64
#define NCLS  10

// Two FMA2s sharing multiplier h in slot %2 -> adjacent + same-slot reuse.
#define FMA2PAIR(accA, accB, hv, wa, wb)                       \
    asm("fma.rn.f32x2 %0, %2, %3, %0;\n\t"                     \
        "fma.rn.f32x2 %1, %2, %4, %1;"                         \
        : "+l"(accA), "+l"(accB)                               \
        : "l"(hv), "l"(wa), "l"(wb))

#define ADD2(d, a, b) \
    asm("add.rn.f32x2 %0, %1, %2;" : "=l"(d) : "l"(a), "l"(b))
#define MUL2(d, a, b) \
    asm("mul.rn.f32x2 %0, %1, %2;" : "=l"(d) : "l"(a), "l"(b))

__device__ __forceinline__ float tanh_fast(float z) {
    float r;
    asm("tanh.approx.f32 %0, %1;" : "=f"(r) : "f"(z));
    return r;
}

__device__ __forceinline__ float pair_sum(unsigned long long a) {
    return __uint_as_float((unsigned)a) + __uint_as_float((unsigned)(a >> 32));
}

__device__ __forceinline__ unsigned long long pack_lo(float x) {
    return (unsigned long long)__float_as_uint(x);   // (x, 0.0f)
}

__global__ __launch_bounds__(128, 3)
void lstm_net_kernel(const float* __restrict__ x,
                     const float* __restrict__ W_ih,
                     const float* __restrict__ W_hh,
                     const float* __restrict__ b_ih,
                     const float* __restrict__ b_hh,
                     const float* __restrict__ fc1_w,
                     const float* __restrict__ fc1_b,
                     const float* __restrict__ fc2_w,
                     const float* __restrict__ fc2_b,
                     float* __restrict__ out)
{
    __shared__ __align__(16) float sx[T_LEN];      // x row (8 KB)
    __shared__ __align__(16) float sh[2][HDIM];    // double-buffered hidden
    __shared__ __align__(16) float s1[HDIM];       // fc1 out

    const int b   = blockIdx.x;
    const int t   = threadIdx.x;
    const int hid = t >> 1;
    const int p   = t & 1;
    const int r0  = (2 * p) * HDIM + hid;          // i (p=0) / g (p=1)
    const int r1  = (2 * p + 1) * HDIM + hid;      // f (p=0) / o (p=1)

    // ---- phase-skew spin: de-convoy the 3 co-resident CTAs ----
    {
        const int n = (int)(blockIdx.x % 3u) * 60;
        float z = 1.0f;
        #pragma unroll 1
        for (int i = 0; i < n; i++) z = fmaf(z, 1.0000001f, 1e-7f);
        asm volatile("" :: "f"(z));
    }

    // ---- stage x[b,:] (coalesced float4) ----
    {
        const float4* xr = reinterpret_cast<const float4*>(x + (size_t)b * T_LEN);
        float4* sx4 = reinterpret_cast<float4*>(sx);
        #pragma unroll
        for (int i = t; i < T_LEN / 4; i += 128) sx4[i] = xr[i];
    }

    // ---- both full W_hh rows -> 64 packed u64 regs, pre-scaled ----
    // row0: p=0 i (sigmoid, x0.5), p=1 g (tanh, x1). row1 (f or o): sigmoid, x0.5.
    const float sc0 = p ? 1.0f : 0.5f;
    unsigned long long w0[32], w1[32];
    {
        unsigned long long s0p, s1p;
        {
            const unsigned u0 = __float_as_uint(sc0);
            const unsigned uh = __float_as_uint(0.5f);
            s0p = ((unsigned long long)u0 << 32) | u0;
            s1p = ((unsigned long long)uh << 32) | uh;
        }
        const ulonglong2* p0 = reinterpret_cast<const ulonglong2*>(W_hh + (size_t)r0 * HDIM);
        const ulonglong2* p1 = reinterpret_cast<const ulonglong2*>(W_hh + (size_t)r1 * HDIM);
        #pragma unroll
        for (int j = 0; j < 16; j++) {
            ulonglong2 v0 = p0[j];
            MUL2(w0[2 * j],     v0.x, s0p);
            MUL2(w0[2 * j + 1], v0.y, s0p);
            ulonglong2 v1 = p1[j];
            MUL2(w1[2 * j],     v1.x, s1p);
            MUL2(w1[2 * j + 1], v1.y, s1p);
        }
    }
    const float w_in0 = W_ih[r0] * sc0;
    const float w_in1 = W_ih[r1] * 0.5f;
    const float bias0 = (b_ih[r0] + b_hh[r0]) * sc0;
    const float bias1 = (b_ih[r1] + b_hh[r1]) * 0.5f;

    // row0 activation: p=0 -> sigmoid (i), p=1 -> tanh (g). row1 always sigmoid.
    const float aa0 = p ? 1.0f : 0.5f;
    const float ab0 = p ? 0.0f : 0.5f;

    if (t < HDIM) sh[0][t] = 0.0f;
    float c = 0.0f;
    __syncthreads();

    // one LSTM step: read sh[RB], write sh[RB^1]
    #define LSTM_STEP(RB, XT)                                                        \
    {                                                                                \
        const float pre0 = fmaf((XT), w_in0, bias0);                                 \
        const float pre1 = fmaf((XT), w_in1, bias1);                                 \
        const ulonglong2* hp = reinterpret_cast<const ulonglong2*>(sh[RB]);          \
        unsigned long long A0 = pack_lo(pre0), A1 = 0ull;                            \
        unsigned long long B0 = pack_lo(pre1), B1 = 0ull;                            \
        _Pragma("unroll")                                                            \
        for (int j = 0; j < 4; j++) {                                                \
            ulonglong2 h0 = hp[4 * j + 0], h1 = hp[4 * j + 1];                       \
            ulonglong2 h2 = hp[4 * j + 2], h3 = hp[4 * j + 3];                       \
            FMA2PAIR(A0, B0, h0.x, w0[8 * j + 0], w1[8 * j + 0]);                    \
            FMA2PAIR(A1, B1, h0.y, w0[8 * j + 1], w1[8 * j + 1]);                    \
            FMA2PAIR(A0, B0, h1.x, w0[8 * j + 2], w1[8 * j + 2]);                    \
            FMA2PAIR(A1, B1, h1.y, w0[8 * j + 3], w1[8 * j + 3]);                    \
            FMA2PAIR(A0, B0, h2.x, w0[8 * j + 4], w1[8 * j + 4]);                    \
            FMA2PAIR(A1, B1, h2.y, w0[8 * j + 5], w1[8 * j + 5]);                    \
            FMA2PAIR(A0, B0, h3.x, w0[8 * j + 6], w1[8 * j + 6]);                    \
            FMA2PAIR(A1, B1, h3.y, w0[8 * j + 7], w1[8 * j + 7]);                    \
        }                                                                            \
        unsigned long long As, Bs;                                                   \
        ADD2(As, A0, A1);  ADD2(Bs, B0, B1);                                         \
        float g0 = pair_sum(As);                                                     \
        float g1 = pair_sum(Bs);                                                     \
        float act0 = fmaf(tanh_fast(g0), aa0, ab0);                                  \
        float act1 = fmaf(tanh_fast(g1), 0.5f, 0.5f);                                \
        float othA = __shfl_xor_sync(0xffffffffu, act0, 1, 2);                       \
        float othB = __shfl_xor_sync(0xffffffffu, act1, 1, 2);                       \
        float iv = p ? othA : act0;                                                  \
        float fv = p ? othB : act1;                                                  \
        float gv = p ? act0 : othA;                                                  \
        float ov = p ? act1 : othB;                                                  \
        c = fmaf(fv, c, iv * gv);                                                    \
        float hnew = ov * tanh_fast(c);                                              \
        if (p == 0) sh[(RB) ^ 1][hid] = hnew;                                        \
        __syncthreads();                                                             \
    }

    #pragma unroll 1
    for (int step = 0; step < T_LEN; step += 4) {
        const float4 xv = *reinterpret_cast<const float4*>(&sx[step]);
        LSTM_STEP(0, xv.x)
        LSTM_STEP(1, xv.y)
        LSTM_STEP(0, xv.z)
        LSTM_STEP(1, xv.w)
    }
    #undef LSTM_STEP

    // T_LEN % 4 == 0: final h lives in sh[0]
    const float* hf = sh[0];

    // ---- fc1 + relu (64 threads) ----
    if (t < HDIM) {
        float a = fc1_b[t];
        const float* wr = fc1_w + t * HDIM;
        #pragma unroll 16
        for (int k = 0; k < HDIM; k++) a = fmaf(wr[k], hf[k], a);
        s1[t] = fmaxf(a, 0.0f);
    }
    __syncthreads();

    // ---- fc2 (10 threads) ----
    if (t < NCLS) {
        float a = fc2_b[t];
        const float* wr = fc2_w + t * HDIM;
        #pragma unroll 16
        for (int k = 0; k < HDIM; k++) a = fmaf(wr[k], s1[k], a);
        out[(size_t)b * NCLS + t] = a;
    }
}

extern "C" void kernel_launch(void* const* d_in, const int* in_sizes, int n_in,
                              void* d_out, int out_size)
{
    const float* x     = (const float*)d_in[0];
    const float* W_ih  = (const float*)d_in[1];
    const float* W_hh  = (const float*)d_in[2];
    const float* b_ih  = (const float*)d_in[3];
    const float* b_hh  = (const float*)d_in[4];
    const float* fc1_w = (const float*)d_in[5];
    const float* fc1_b = (const float*)d_in[6];
    const float* fc2_w = (const float*)d_in[7];
    const float* fc2_b = (const float*)d_in[8];
    float* out = (float*)d_out;

    const int B = in_sizes[0] / T_LEN;   // 1024

    lstm_net_kernel<<<B, 128>>>(x, W_ih, W_hh, b_ih, b_hh,
                                fc1_w, fc1_b, fc2_w, fc2_b, out);
}